// round 8
// baseline (speedup 1.0000x reference)
#include <cuda_runtime.h>
#include <cuda_bf16.h>
#include <cstdint>
#include <cstddef>

// ============================================================================
// TripletSTDP: B=32, T=512, N_PRE=N_POST=1024.
// wu = (1/(B*T)) * (A @ B^T), K = 2*B*T = 32768
//   A[m][k]: k<16384 -> R trace of pre (decayed), k>=16384 -> pre spike
//   B[n][k]: k<16384 -> post spike,               k>=16384 -> -O trace of post
// A/B PRE-PERMUTED in mma.m16n8k16 fragment order (bf16).
// GEMM: persistent over 148 CTAs; work = 16384 chunk-units (32 tiles of
// 128x256 x 512 k64-chunks); CTA c owns global chunks [c*4096/37,(c+1)*4096/37)
// (exact partition, <=2 tiles/CTA); partials to WS[cta][slot]; deterministic
// static-schedule reduce reconstructs each tile from overlapping CTAs.
// ============================================================================

static __device__ __align__(128) __nv_bfloat16 g_A[1024ull * 32768ull]; // 64 MB
static __device__ __align__(128) __nv_bfloat16 g_B[1024ull * 32768ull]; // 64 MB
static __device__ __align__(128) float g_WS2[148ull * 2ull * 32768ull]; // 38.8 MB partials

// ---------------------------------------------------------------------------
__device__ __forceinline__ void mma_bf16(float* d, const uint32_t* a,
                                         uint32_t b0, uint32_t b1) {
    asm volatile(
        "mma.sync.aligned.m16n8k16.row.col.f32.bf16.bf16.f32 "
        "{%0,%1,%2,%3}, {%4,%5,%6,%7}, {%8,%9}, {%0,%1,%2,%3};"
        : "+f"(d[0]), "+f"(d[1]), "+f"(d[2]), "+f"(d[3])
        : "r"(a[0]), "r"(a[1]), "r"(a[2]), "r"(a[3]), "r"(b0), "r"(b1));
}
__device__ __forceinline__ uint32_t smem_u32(const void* p) {
    uint32_t a;
    asm("{ .reg .u64 t; cvta.to.shared.u64 t, %1; cvt.u32.u64 %0, t; }" : "=r"(a) : "l"(p));
    return a;
}
__device__ __forceinline__ void cp16(uint32_t dst, const void* src) {
    asm volatile("cp.async.cg.shared.global [%0], [%1], 16;" :: "r"(dst), "l"(src));
}

// ---------------------------------------------------------------------------
// Kernel 1: trace scan + fragment-layout store (R7 verbatim; 41.8us).
// ---------------------------------------------------------------------------
__global__ void __launch_bounds__(128) stdp_scan_kernel(const float* __restrict__ pre,
                                                        const float* __restrict__ post)
{
    const int side = blockIdx.z;
    const float* __restrict__ in = side ? post : pre;
    __nv_bfloat16* mat = side ? g_B : g_A;
    const int b   = blockIdx.y;
    const int bx  = blockIdx.x;
    const int tid = threadIdx.x;
    const int p0  = bx * 128;

    const float dA = 0.95122942f;                      // exp(-1/20)
    const float dB = side ? 0.99126643f : 0.99014786f; // exp(-1/114) / exp(-1/101)
    const float c1 = side ? 0.00525f : 0.005f;         // A_MINUS / A_PLUS
    const float c2 = 0.0001f;

    __shared__ __align__(16) float         sx[2][32 * 128];
    __shared__ __align__(16) __nv_bfloat16 s1[128][40];
    __shared__ __align__(16) __nv_bfloat16 s2[128][40];

    const float* base = in + (size_t)b * (512 * 1024) + p0;
    const uint32_t sxb = smem_u32(sx);

    auto fill = [&](int ch, int s) {
        const float* g = base + (size_t)ch * 32 * 1024;
        uint32_t st = sxb + (uint32_t)s * (32 * 128 * 4);
        #pragma unroll
        for (int i = 0; i < 8; ++i) {
            int idx = tid + i * 128;
            int r = idx >> 5, j = idx & 31;
            cp16(st + (uint32_t)(r * 512 + j * 16), g + (size_t)r * 1024 + j * 4);
        }
    };

    fill(0, 0);
    asm volatile("cp.async.commit_group;" ::: "memory");

    float t1 = 0.f, t2 = 0.f;

    for (int ch = 0; ch < 16; ++ch) {
        asm volatile("cp.async.wait_group 0;" ::: "memory");
        __syncthreads();
        if (ch + 1 < 16) fill(ch + 1, (ch + 1) & 1);
        asm volatile("cp.async.commit_group;" ::: "memory");

        const float* x_s = sx[ch & 1];
        #pragma unroll
        for (int tt = 0; tt < 32; ++tt) {
            float x = x_s[tt * 128 + tid];
            t1 *= dA; t2 *= dB;
            float tr = fmaf(c2 * t1, t2, c1 * t1);
            s1[tid][tt] = __float2bfloat16(side ? x : tr);
            s2[tid][tt] = __float2bfloat16(side ? -tr : x);
            t1 += x; t2 += x;
        }
        __syncthreads();

        const int ksbase = b * 32 + ch * 2;
        uint4* mat4 = reinterpret_cast<uint4*>(mat);
        #pragma unroll
        for (int it = 0; it < 4; ++it) {
            int f    = it * 128 + tid;
            int lane = f & 31;
            int ksl  = (f >> 5) & 1;
            int frag = f >> 6;
            int gid  = lane >> 2, tig = lane & 3;
            int pr   = frag * 16 + gid;
            int tb   = ksl * 16 + tig * 2;
            uint4 w1, w2;
            w1.x = *(const uint32_t*)&s1[pr    ][tb    ];
            w1.y = *(const uint32_t*)&s1[pr + 8][tb    ];
            w1.z = *(const uint32_t*)&s1[pr    ][tb + 8];
            w1.w = *(const uint32_t*)&s1[pr + 8][tb + 8];
            w2.x = *(const uint32_t*)&s2[pr    ][tb    ];
            w2.y = *(const uint32_t*)&s2[pr + 8][tb    ];
            w2.z = *(const uint32_t*)&s2[pr    ][tb + 8];
            w2.w = *(const uint32_t*)&s2[pr + 8][tb + 8];
            int ks = ksbase + ksl;
            size_t d16, half;
            if (side == 0) {
                d16  = ((size_t)(bx * 2048 + ks) * 8 + frag) * 32 + lane;
                half = 1024ull * 8 * 32;
            } else {
                d16  = ((size_t)((bx >> 1) * 2048 + ks) * 16 + (bx & 1) * 8 + frag) * 32 + lane;
                half = 1024ull * 16 * 32;
            }
            mat4[d16]        = w1;
            mat4[d16 + half] = w2;
        }
        __syncthreads();
    }
}

// ---------------------------------------------------------------------------
// Kernel 2: persistent bf16 mma.sync GEMM. 148 CTAs, 256 threads (2Mx4N warps,
// warp tile 64x64), tile 128x256, k64 chunks, 4-stage cp.async + reg prefetch.
// ---------------------------------------------------------------------------
constexpr int      CHUNK_U4    = 3072;                       // 1024 A + 2048 B uint4
constexpr uint32_t GEMM_SMEM_B = 4 * CHUNK_U4 * 16;          // 196608 B

__global__ void __launch_bounds__(256, 1) stdp_gemm_kernel()
{
    extern __shared__ __align__(16) uint4 sm[];              // [4][3072]
    const int tid  = threadIdx.x;
    const int lane = tid & 31;
    const int wid  = tid >> 5;
    const int wm   = wid & 1;
    const int wn   = wid >> 1;
    const int cta  = blockIdx.x;
    const int gid  = lane >> 2, tig = lane & 3;

    const int g0 = (cta * 4096) / 37;          // global chunk range [g0, g1)
    const int g1 = ((cta + 1) * 4096) / 37;
    const int t0 = g0 >> 9;                    // first tile (0..31)
    const int end0 = min(g1, (t0 + 1) << 9);

    const uint32_t smb = smem_u32(sm);

    auto process = [&](int tile, int l0, int L, int slot) {
        const int mt = tile >> 2, nt = tile & 3;
        const uint4* gA = reinterpret_cast<const uint4*>(g_A)
                        + (size_t)mt * 524288 + (size_t)l0 * 1024;
        const uint4* gB = reinterpret_cast<const uint4*>(g_B)
                        + (size_t)nt * 1048576 + (size_t)l0 * 2048;

        auto fill = [&](int c, int s) {
            uint32_t stA = smb + (uint32_t)s * (CHUNK_U4 * 16);
            uint32_t stB = stA + 1024 * 16;
            const uint4* srcA = gA + (size_t)c * 1024;
            const uint4* srcB = gB + (size_t)c * 2048;
            #pragma unroll
            for (int i = 0; i < 4; ++i)
                cp16(stA + (uint32_t)(tid + i * 256) * 16, srcA + tid + i * 256);
            #pragma unroll
            for (int i = 0; i < 8; ++i)
                cp16(stB + (uint32_t)(tid + i * 256) * 16, srcB + tid + i * 256);
        };
        auto aAddr = [&](int c, int ksl, int i) -> const uint4* {
            return sm + (c & 3) * CHUNK_U4 + (size_t)(ksl * 8 + wm * 4 + i) * 32 + lane;
        };
        auto bAddr = [&](int c, int ksl, int j) -> const uint4* {
            return sm + (c & 3) * CHUNK_U4 + 1024 + (size_t)(ksl * 16 + wn * 4 + j) * 32 + lane;
        };

        float acc[4][8][4];
        #pragma unroll
        for (int i = 0; i < 4; ++i)
            #pragma unroll
            for (int j = 0; j < 8; ++j)
                #pragma unroll
                for (int v = 0; v < 4; ++v) acc[i][j][v] = 0.f;

        #pragma unroll
        for (int f = 0; f < 3; ++f) {
            if (f < L) fill(f, f);
            asm volatile("cp.async.commit_group;" ::: "memory");
        }
        asm volatile("cp.async.wait_group 1;" ::: "memory");
        __syncthreads();

        uint4 af[2][4], bf[2][4];
        #pragma unroll
        for (int i = 0; i < 4; ++i) af[0][i] = *aAddr(0, 0, i);
        #pragma unroll
        for (int j = 0; j < 4; ++j) bf[0][j] = *bAddr(0, 0, j);

        for (int c = 0; c < L; ++c) {
            #pragma unroll
            for (int ksl = 0; ksl < 4; ++ksl) {
                const int cur = ksl & 1;
                const int nxt = cur ^ 1;
                const int pc  = (ksl == 3) ? (c + 1) : c;  // chunk c+1 resident via wait_group(1);
                const int pk  = (ksl + 1) & 3;             // c=L-1 prefetch dead but safe
                #pragma unroll
                for (int i = 0; i < 4; ++i) af[nxt][i] = *aAddr(pc, pk, i);
                #pragma unroll
                for (int j = 0; j < 4; ++j) bf[nxt][j] = *bAddr(pc, pk, j);
                #pragma unroll
                for (int i = 0; i < 4; ++i) {
                    const uint32_t* a = reinterpret_cast<const uint32_t*>(&af[cur][i]);
                    #pragma unroll
                    for (int j = 0; j < 4; ++j) {
                        mma_bf16(acc[i][2 * j + 0], a, bf[cur][j].x, bf[cur][j].z);
                        mma_bf16(acc[i][2 * j + 1], a, bf[cur][j].y, bf[cur][j].w);
                    }
                }
            }
            if (c + 3 < L) fill(c + 3, (c + 3) & 3);
            asm volatile("cp.async.commit_group;" ::: "memory");
            asm volatile("cp.async.wait_group 1;" ::: "memory");
            __syncthreads();
        }

        // write tile-local partial (128x256) to WS[cta][slot]
        float* ws = g_WS2 + ((size_t)(cta * 2 + slot) << 15);
        #pragma unroll
        for (int i = 0; i < 4; ++i) {
            int r0 = (wm * 4 + i) * 16 + gid;
            #pragma unroll
            for (int j = 0; j < 8; ++j) {
                int cl = (wn * 4 + (j >> 1)) * 16 + (j & 1) * 8 + tig * 2;
                float* d0 = ws + (size_t)r0 * 256 + cl;
                d0[0] = acc[i][j][0];
                d0[1] = acc[i][j][1];
                float* d1 = d0 + 8 * 256;
                d1[0] = acc[i][j][2];
                d1[1] = acc[i][j][3];
            }
        }
    };

    process(t0, g0 - (t0 << 9), end0 - g0, 0);
    if (g1 > end0) {
        process(t0 + 1, 0, g1 - end0, 1);
    } else {
        float4 z = make_float4(0.f, 0.f, 0.f, 0.f);
        float4* p = reinterpret_cast<float4*>(g_WS2 + ((size_t)(cta * 2 + 1) << 15));
        #pragma unroll
        for (int k = 0; k < 32; ++k) p[tid + k * 256] = z;
    }
}

// ---------------------------------------------------------------------------
// Kernel 3: gather overlapping CTA partials per tile + scale. Deterministic
// (overlap set derived from the same static split points).
// ---------------------------------------------------------------------------
__global__ void __launch_bounds__(256) stdp_reduce_kernel(float* __restrict__ out)
{
    int gi   = blockIdx.x * 256 + threadIdx.x;     // float4 units, 0..262143
    int row  = gi >> 8;
    int colq = gi & 255;                           // float4 column index
    int t    = (row >> 7) * 4 + (colq >> 6);       // tile (128x256): col>>8 == colq>>6
    int e4   = (row & 127) * 64 + (colq & 63);     // float4 offset within tile

    float x = 0.f, y = 0.f, z = 0.f, w = 0.f;
    int c0 = (37 * t) >> 3;                        // CTA containing chunk 512t (or one before)
    for (int c = c0; c < 148; ++c) {
        int sc = (c * 4096) / 37;
        if (sc >= ((t + 1) << 9)) break;
        int sc1 = ((c + 1) * 4096) / 37;
        if (sc1 <= (t << 9)) continue;
        int slot = ((sc >> 9) == t) ? 0 : 1;
        const float4 v = reinterpret_cast<const float4*>(
            g_WS2 + ((size_t)(c * 2 + slot) << 15))[e4];
        x += v.x; y += v.y; z += v.z; w += v.w;
    }
    const float s = 1.0f / 16384.0f;
    float4 r; r.x = x * s; r.y = y * s; r.z = z * s; r.w = w * s;
    reinterpret_cast<float4*>(out)[gi] = r;
}

// ---------------------------------------------------------------------------
extern "C" void kernel_launch(void* const* d_in, const int* in_sizes, int n_in,
                              void* d_out, int out_size)
{
    (void)in_sizes; (void)n_in; (void)out_size;
    const float* pre  = (const float*)d_in[0];
    const float* post = (const float*)d_in[1];
    float* out = (float*)d_out;

    stdp_scan_kernel<<<dim3(8, 32, 2), 128>>>(pre, post);

    cudaFuncSetAttribute(stdp_gemm_kernel,
                         cudaFuncAttributeMaxDynamicSharedMemorySize, GEMM_SMEM_B);
    stdp_gemm_kernel<<<148, 256, GEMM_SMEM_B>>>();

    stdp_reduce_kernel<<<1024, 256>>>(out);
}

// round 9
// speedup vs baseline: 1.0989x; 1.0989x over previous
#include <cuda_runtime.h>
#include <cuda_bf16.h>
#include <cstdint>
#include <cstddef>

// ============================================================================
// TripletSTDP: B=32, T=512, N_PRE=N_POST=1024.
// wu = (1/(B*T)) * (A @ B^T), K = 2*B*T = 32768
//   A[m][k]: k<16384 -> R trace of pre (decayed), k>=16384 -> pre spike
//   B[n][k]: k<16384 -> post spike,               k>=16384 -> -O trace of post
// A/B PRE-PERMUTED in mma.m16n8k16 fragment order (bf16).
// GEMM/reduce = R7 verbatim (best: grid 8x4x4 keeps concurrent L2 sharing).
// Scan: 16-step input chunks, 4 cp.async stages, wait_group(2) -> 3 chunks
// in flight per CTA (latency-bound fix).
// ============================================================================

static __device__ __align__(128) __nv_bfloat16 g_A[1024ull * 32768ull]; // 64 MB
static __device__ __align__(128) __nv_bfloat16 g_B[1024ull * 32768ull]; // 64 MB
static __device__ __align__(128) float         g_WS[4ull * 1024ull * 1024ull]; // split-K partials

// ---------------------------------------------------------------------------
__device__ __forceinline__ void mma_bf16(float* d, const uint32_t* a,
                                         uint32_t b0, uint32_t b1) {
    asm volatile(
        "mma.sync.aligned.m16n8k16.row.col.f32.bf16.bf16.f32 "
        "{%0,%1,%2,%3}, {%4,%5,%6,%7}, {%8,%9}, {%0,%1,%2,%3};"
        : "+f"(d[0]), "+f"(d[1]), "+f"(d[2]), "+f"(d[3])
        : "r"(a[0]), "r"(a[1]), "r"(a[2]), "r"(a[3]), "r"(b0), "r"(b1));
}
__device__ __forceinline__ uint32_t smem_u32(const void* p) {
    uint32_t a;
    asm("{ .reg .u64 t; cvta.to.shared.u64 t, %1; cvt.u32.u64 %0, t; }" : "=r"(a) : "l"(p));
    return a;
}
__device__ __forceinline__ void cp16(uint32_t dst, const void* src) {
    asm volatile("cp.async.cg.shared.global [%0], [%1], 16;" :: "r"(dst), "l"(src));
}

// ---------------------------------------------------------------------------
// Kernel 1: trace scan + fragment-layout store. grid (8,32,2), 128 threads.
// 32 chunks of 16 t-steps; 4-stage cp.async input pipeline, 3 chunks in flight.
// ---------------------------------------------------------------------------
__global__ void __launch_bounds__(128) stdp_scan_kernel(const float* __restrict__ pre,
                                                        const float* __restrict__ post)
{
    const int side = blockIdx.z;
    const float* __restrict__ in = side ? post : pre;
    __nv_bfloat16* mat = side ? g_B : g_A;
    const int b   = blockIdx.y;
    const int bx  = blockIdx.x;
    const int tid = threadIdx.x;
    const int p0  = bx * 128;

    const float dA = 0.95122942f;                      // exp(-1/20)
    const float dB = side ? 0.99126643f : 0.99014786f; // exp(-1/114) / exp(-1/101)
    const float c1 = side ? 0.00525f : 0.005f;         // A_MINUS / A_PLUS
    const float c2 = 0.0001f;

    __shared__ __align__(16) float         sx[4][16 * 128];  // 4 x 8 KB input stages
    __shared__ __align__(16) __nv_bfloat16 s1[128][24];      // pad 24: conflict-free
    __shared__ __align__(16) __nv_bfloat16 s2[128][24];

    const float* base = in + (size_t)b * (512 * 1024) + p0;
    const uint32_t sxb = smem_u32(sx);

    // fill chunk ch (16 rows x 512 B) into stage s
    auto fill = [&](int ch, int s) {
        const float* g = base + (size_t)ch * 16 * 1024;
        uint32_t st = sxb + (uint32_t)s * (16 * 128 * 4);
        #pragma unroll
        for (int i = 0; i < 4; ++i) {
            int idx = tid + i * 128;          // 0..511
            int r = idx >> 5, j = idx & 31;
            cp16(st + (uint32_t)(r * 512 + j * 16), g + (size_t)r * 1024 + j * 4);
        }
    };

    #pragma unroll
    for (int f = 0; f < 3; ++f) {
        fill(f, f);
        asm volatile("cp.async.commit_group;" ::: "memory");
    }

    float t1 = 0.f, t2 = 0.f;

    for (int ch = 0; ch < 32; ++ch) {
        asm volatile("cp.async.wait_group 2;" ::: "memory");  // chunk ch arrived
        __syncthreads();   // sx visibility; also guards s1/s2 overwrite vs prev transpose
        if (ch + 3 < 32) fill(ch + 3, (ch + 3) & 3);
        asm volatile("cp.async.commit_group;" ::: "memory");

        const float* x_s = sx[ch & 3];
        #pragma unroll
        for (int tt = 0; tt < 16; ++tt) {
            float x = x_s[tt * 128 + tid];
            t1 *= dA; t2 *= dB;                          // decay first
            float tr = fmaf(c2 * t1, t2, c1 * t1);       // c1*r1 + c2*r1*r2
            s1[tid][tt] = __float2bfloat16(side ? x : tr);
            s2[tid][tt] = __float2bfloat16(side ? -tr : x);
            t1 += x; t2 += x;                            // then add spike
        }
        __syncthreads();                                 // s1/s2 ready for transpose

        const int ks = b * 32 + ch;                      // global k16-step index
        uint4* mat4 = reinterpret_cast<uint4*>(mat);
        #pragma unroll
        for (int it = 0; it < 2; ++it) {
            int f    = it * 128 + tid;                   // slot id 0..255
            int lane = f & 31;
            int frag = f >> 5;                           // 0..7
            int gid  = lane >> 2, tig = lane & 3;
            int pr   = frag * 16 + gid;
            int tb   = tig * 2;
            uint4 w1, w2;
            w1.x = *(const uint32_t*)&s1[pr    ][tb    ];
            w1.y = *(const uint32_t*)&s1[pr + 8][tb    ];
            w1.z = *(const uint32_t*)&s1[pr    ][tb + 8];
            w1.w = *(const uint32_t*)&s1[pr + 8][tb + 8];
            w2.x = *(const uint32_t*)&s2[pr    ][tb    ];
            w2.y = *(const uint32_t*)&s2[pr + 8][tb    ];
            w2.z = *(const uint32_t*)&s2[pr    ][tb + 8];
            w2.w = *(const uint32_t*)&s2[pr + 8][tb + 8];
            size_t d16, half;
            if (side == 0) {   // A layout
                d16  = ((size_t)(bx * 2048 + ks) * 8 + frag) * 32 + lane;
                half = 1024ull * 8 * 32;
            } else {           // B layout
                d16  = ((size_t)((bx >> 1) * 2048 + ks) * 16 + (bx & 1) * 8 + frag) * 32 + lane;
                half = 1024ull * 16 * 32;
            }
            mat4[d16]        = w1;
            mat4[d16 + half] = w2;
        }
        // next iteration's post-wait __syncthreads guards s1/s2 reuse
    }
}

// ---------------------------------------------------------------------------
// Kernel 2: bf16 mma.sync GEMM (R7 verbatim; best known). CTA 128x256,
// 8 warps (2Mx4N), warp tile 64x64, split-K=4 -> grid(8,4,4).
// 4-stage cp.async pipeline; wait_group(1) keeps chunks c AND c+1 resident.
// ---------------------------------------------------------------------------
constexpr int      CHUNK_U4    = 3072;                       // 1024 A + 2048 B uint4
constexpr uint32_t GEMM_SMEM_B = 4 * CHUNK_U4 * 16;          // 196608 B

__global__ void __launch_bounds__(256, 1) stdp_gemm_kernel()
{
    extern __shared__ __align__(16) uint4 sm[];              // [4][3072]
    const int tid  = threadIdx.x;
    const int lane = tid & 31;
    const int wid  = tid >> 5;
    const int wm   = wid & 1;
    const int wn   = wid >> 1;
    const int mt   = blockIdx.x;
    const int nt   = blockIdx.y;
    const int kz   = blockIdx.z;

    const uint4* gA = reinterpret_cast<const uint4*>(g_A)
                    + (size_t)(mt * 2048 + kz * 512) * 8 * 32;
    const uint4* gB = reinterpret_cast<const uint4*>(g_B)
                    + (size_t)(nt * 2048 + kz * 512) * 16 * 32;

    const uint32_t smb = smem_u32(sm);

    auto fill = [&](int c, int s) {
        uint32_t stA = smb + (uint32_t)s * (CHUNK_U4 * 16);
        uint32_t stB = stA + 1024 * 16;
        const uint4* srcA = gA + (size_t)c * 1024;
        const uint4* srcB = gB + (size_t)c * 2048;
        #pragma unroll
        for (int i = 0; i < 4; ++i)
            cp16(stA + (uint32_t)(tid + i * 256) * 16, srcA + tid + i * 256);
        #pragma unroll
        for (int i = 0; i < 8; ++i)
            cp16(stB + (uint32_t)(tid + i * 256) * 16, srcB + tid + i * 256);
    };
    auto aAddr = [&](int c, int ksl, int i) -> const uint4* {
        return sm + (c & 3) * CHUNK_U4 + (size_t)(ksl * 8 + wm * 4 + i) * 32 + lane;
    };
    auto bAddr = [&](int c, int ksl, int j) -> const uint4* {
        return sm + (c & 3) * CHUNK_U4 + 1024 + (size_t)(ksl * 16 + wn * 4 + j) * 32 + lane;
    };

    float acc[4][8][4];
    #pragma unroll
    for (int i = 0; i < 4; ++i)
        #pragma unroll
        for (int j = 0; j < 8; ++j)
            #pragma unroll
            for (int c = 0; c < 4; ++c) acc[i][j][c] = 0.f;

    #pragma unroll
    for (int f = 0; f < 3; ++f) {
        fill(f, f);
        asm volatile("cp.async.commit_group;" ::: "memory");
    }
    asm volatile("cp.async.wait_group 1;" ::: "memory");
    __syncthreads();

    uint4 af[2][4], bf[2][4];
    #pragma unroll
    for (int i = 0; i < 4; ++i) af[0][i] = *aAddr(0, 0, i);
    #pragma unroll
    for (int j = 0; j < 4; ++j) bf[0][j] = *bAddr(0, 0, j);

    for (int c = 0; c < 128; ++c) {
        #pragma unroll
        for (int ksl = 0; ksl < 4; ++ksl) {
            const int cur = ksl & 1;
            const int nxt = cur ^ 1;
            const int pc  = (ksl == 3) ? (c + 1) : c;  // c+1 resident via wait_group(1);
            const int pk  = (ksl + 1) & 3;             // c=127 prefetch dead but safe
            #pragma unroll
            for (int i = 0; i < 4; ++i) af[nxt][i] = *aAddr(pc, pk, i);
            #pragma unroll
            for (int j = 0; j < 4; ++j) bf[nxt][j] = *bAddr(pc, pk, j);
            #pragma unroll
            for (int i = 0; i < 4; ++i) {
                const uint32_t* a = reinterpret_cast<const uint32_t*>(&af[cur][i]);
                #pragma unroll
                for (int j = 0; j < 4; ++j) {
                    mma_bf16(acc[i][2 * j + 0], a, bf[cur][j].x, bf[cur][j].z);
                    mma_bf16(acc[i][2 * j + 1], a, bf[cur][j].y, bf[cur][j].w);
                }
            }
        }
        if (c + 3 < 128) fill(c + 3, (c + 3) & 3);
        asm volatile("cp.async.commit_group;" ::: "memory");
        asm volatile("cp.async.wait_group 1;" ::: "memory");
        __syncthreads();
    }

    const int gid = lane >> 2, tig = lane & 3;
    float* wsbase = g_WS + ((size_t)kz << 20);
    #pragma unroll
    for (int i = 0; i < 4; ++i) {
        int row0 = mt * 128 + (wm * 4 + i) * 16 + gid;
        #pragma unroll
        for (int j = 0; j < 8; ++j) {
            int col = nt * 256 + (wn * 4 + (j >> 1)) * 16 + (j & 1) * 8 + tig * 2;
            float* d0 = wsbase + (size_t)row0 * 1024 + col;
            d0[0] = acc[i][j][0];
            d0[1] = acc[i][j][1];
            float* d1 = d0 + 8 * 1024;
            d1[0] = acc[i][j][2];
            d1[1] = acc[i][j][3];
        }
    }
}

// ---------------------------------------------------------------------------
// Kernel 3: reduce split-K partials + scale 1/(B*T). Deterministic.
// ---------------------------------------------------------------------------
__global__ void __launch_bounds__(256) stdp_reduce_kernel(float* __restrict__ out)
{
    int i = blockIdx.x * 256 + threadIdx.x;
    const float4* w = reinterpret_cast<const float4*>(g_WS);
    float4 a = w[i];
    float4 b = w[i + 262144];
    float4 c = w[i + 524288];
    float4 d = w[i + 786432];
    const float s = 1.0f / 16384.0f;
    float4 r;
    r.x = (a.x + b.x + c.x + d.x) * s;
    r.y = (a.y + b.y + c.y + d.y) * s;
    r.z = (a.z + b.z + c.z + d.z) * s;
    r.w = (a.w + b.w + c.w + d.w) * s;
    reinterpret_cast<float4*>(out)[i] = r;
}

// ---------------------------------------------------------------------------
extern "C" void kernel_launch(void* const* d_in, const int* in_sizes, int n_in,
                              void* d_out, int out_size)
{
    (void)in_sizes; (void)n_in; (void)out_size;
    const float* pre  = (const float*)d_in[0];
    const float* post = (const float*)d_in[1];
    float* out = (float*)d_out;

    stdp_scan_kernel<<<dim3(8, 32, 2), 128>>>(pre, post);

    cudaFuncSetAttribute(stdp_gemm_kernel,
                         cudaFuncAttributeMaxDynamicSharedMemorySize, GEMM_SMEM_B);
    stdp_gemm_kernel<<<dim3(8, 4, 4), 256, GEMM_SMEM_B>>>();

    stdp_reduce_kernel<<<1024, 256>>>(out);
}

// round 10
// speedup vs baseline: 1.1224x; 1.0214x over previous
#include <cuda_runtime.h>
#include <cuda_bf16.h>
#include <cstdint>
#include <cstddef>

// ============================================================================
// TripletSTDP: B=32, T=512, N_PRE=N_POST=1024.
// wu = (1/(B*T)) * (A @ B^T), K = 2*B*T = 32768
//   A[m][k]: k<16384 -> R trace of pre (decayed), k>=16384 -> pre spike
//   B[n][k]: k<16384 -> post spike,               k>=16384 -> -O trace of post
// A/B PRE-PERMUTED in mma.m16n8k16 fragment order (bf16).
// Scan = R9 (41us, at its occupancy/latency equilibrium).
// GEMM: grid 8x4x4 (L2-sharing wave), 4-stage cp.async grouped as 2 pairs,
// ONE barrier per 2 k64 chunks (super-chunk), register fragment prefetch.
// ============================================================================

static __device__ __align__(128) __nv_bfloat16 g_A[1024ull * 32768ull]; // 64 MB
static __device__ __align__(128) __nv_bfloat16 g_B[1024ull * 32768ull]; // 64 MB
static __device__ __align__(128) float         g_WS[4ull * 1024ull * 1024ull]; // split-K partials

// ---------------------------------------------------------------------------
__device__ __forceinline__ void mma_bf16(float* d, const uint32_t* a,
                                         uint32_t b0, uint32_t b1) {
    asm volatile(
        "mma.sync.aligned.m16n8k16.row.col.f32.bf16.bf16.f32 "
        "{%0,%1,%2,%3}, {%4,%5,%6,%7}, {%8,%9}, {%0,%1,%2,%3};"
        : "+f"(d[0]), "+f"(d[1]), "+f"(d[2]), "+f"(d[3])
        : "r"(a[0]), "r"(a[1]), "r"(a[2]), "r"(a[3]), "r"(b0), "r"(b1));
}
__device__ __forceinline__ uint32_t smem_u32(const void* p) {
    uint32_t a;
    asm("{ .reg .u64 t; cvta.to.shared.u64 t, %1; cvt.u32.u64 %0, t; }" : "=r"(a) : "l"(p));
    return a;
}
__device__ __forceinline__ void cp16(uint32_t dst, const void* src) {
    asm volatile("cp.async.cg.shared.global [%0], [%1], 16;" :: "r"(dst), "l"(src));
}

// ---------------------------------------------------------------------------
// Kernel 1: trace scan + fragment-layout store (R9 verbatim; 41us).
// ---------------------------------------------------------------------------
__global__ void __launch_bounds__(128) stdp_scan_kernel(const float* __restrict__ pre,
                                                        const float* __restrict__ post)
{
    const int side = blockIdx.z;
    const float* __restrict__ in = side ? post : pre;
    __nv_bfloat16* mat = side ? g_B : g_A;
    const int b   = blockIdx.y;
    const int bx  = blockIdx.x;
    const int tid = threadIdx.x;
    const int p0  = bx * 128;

    const float dA = 0.95122942f;                      // exp(-1/20)
    const float dB = side ? 0.99126643f : 0.99014786f; // exp(-1/114) / exp(-1/101)
    const float c1 = side ? 0.00525f : 0.005f;         // A_MINUS / A_PLUS
    const float c2 = 0.0001f;

    __shared__ __align__(16) float         sx[4][16 * 128];
    __shared__ __align__(16) __nv_bfloat16 s1[128][24];
    __shared__ __align__(16) __nv_bfloat16 s2[128][24];

    const float* base = in + (size_t)b * (512 * 1024) + p0;
    const uint32_t sxb = smem_u32(sx);

    auto fill = [&](int ch, int s) {
        const float* g = base + (size_t)ch * 16 * 1024;
        uint32_t st = sxb + (uint32_t)s * (16 * 128 * 4);
        #pragma unroll
        for (int i = 0; i < 4; ++i) {
            int idx = tid + i * 128;
            int r = idx >> 5, j = idx & 31;
            cp16(st + (uint32_t)(r * 512 + j * 16), g + (size_t)r * 1024 + j * 4);
        }
    };

    #pragma unroll
    for (int f = 0; f < 3; ++f) {
        fill(f, f);
        asm volatile("cp.async.commit_group;" ::: "memory");
    }

    float t1 = 0.f, t2 = 0.f;

    for (int ch = 0; ch < 32; ++ch) {
        asm volatile("cp.async.wait_group 2;" ::: "memory");
        __syncthreads();
        if (ch + 3 < 32) fill(ch + 3, (ch + 3) & 3);
        asm volatile("cp.async.commit_group;" ::: "memory");

        const float* x_s = sx[ch & 3];
        #pragma unroll
        for (int tt = 0; tt < 16; ++tt) {
            float x = x_s[tt * 128 + tid];
            t1 *= dA; t2 *= dB;
            float tr = fmaf(c2 * t1, t2, c1 * t1);
            s1[tid][tt] = __float2bfloat16(side ? x : tr);
            s2[tid][tt] = __float2bfloat16(side ? -tr : x);
            t1 += x; t2 += x;
        }
        __syncthreads();

        const int ks = b * 32 + ch;
        uint4* mat4 = reinterpret_cast<uint4*>(mat);
        #pragma unroll
        for (int it = 0; it < 2; ++it) {
            int f    = it * 128 + tid;
            int lane = f & 31;
            int frag = f >> 5;
            int gid  = lane >> 2, tig = lane & 3;
            int pr   = frag * 16 + gid;
            int tb   = tig * 2;
            uint4 w1, w2;
            w1.x = *(const uint32_t*)&s1[pr    ][tb    ];
            w1.y = *(const uint32_t*)&s1[pr + 8][tb    ];
            w1.z = *(const uint32_t*)&s1[pr    ][tb + 8];
            w1.w = *(const uint32_t*)&s1[pr + 8][tb + 8];
            w2.x = *(const uint32_t*)&s2[pr    ][tb    ];
            w2.y = *(const uint32_t*)&s2[pr + 8][tb    ];
            w2.z = *(const uint32_t*)&s2[pr    ][tb + 8];
            w2.w = *(const uint32_t*)&s2[pr + 8][tb + 8];
            size_t d16, half;
            if (side == 0) {
                d16  = ((size_t)(bx * 2048 + ks) * 8 + frag) * 32 + lane;
                half = 1024ull * 8 * 32;
            } else {
                d16  = ((size_t)((bx >> 1) * 2048 + ks) * 16 + (bx & 1) * 8 + frag) * 32 + lane;
                half = 1024ull * 16 * 32;
            }
            mat4[d16]        = w1;
            mat4[d16 + half] = w2;
        }
    }
}

// ---------------------------------------------------------------------------
// Kernel 2: bf16 mma.sync GEMM, super-chunked. CTA 128x256, 8 warps (2Mx4N),
// warp tile 64x64, split-K=4 -> grid(8,4,4). 4 stages as 2 pairs; one
// wait+barrier per 2 k64 chunks; fills issued at super-step start into the
// pair freed by the previous barrier.
// ---------------------------------------------------------------------------
constexpr int      CHUNK_U4    = 3072;                       // 1024 A + 2048 B uint4
constexpr uint32_t GEMM_SMEM_B = 4 * CHUNK_U4 * 16;          // 196608 B

__global__ void __launch_bounds__(256, 1) stdp_gemm_kernel()
{
    extern __shared__ __align__(16) uint4 sm[];              // [4][3072]
    const int tid  = threadIdx.x;
    const int lane = tid & 31;
    const int wid  = tid >> 5;
    const int wm   = wid & 1;
    const int wn   = wid >> 1;
    const int mt   = blockIdx.x;
    const int nt   = blockIdx.y;
    const int kz   = blockIdx.z;

    const uint4* gA = reinterpret_cast<const uint4*>(g_A)
                    + (size_t)(mt * 2048 + kz * 512) * 8 * 32;
    const uint4* gB = reinterpret_cast<const uint4*>(g_B)
                    + (size_t)(nt * 2048 + kz * 512) * 16 * 32;

    const uint32_t smb = smem_u32(sm);

    // fill chunk c into stage st (0..3)
    auto fill = [&](int c, int st) {
        uint32_t stA = smb + (uint32_t)st * (CHUNK_U4 * 16);
        uint32_t stB = stA + 1024 * 16;
        const uint4* srcA = gA + (size_t)c * 1024;
        const uint4* srcB = gB + (size_t)c * 2048;
        #pragma unroll
        for (int i = 0; i < 4; ++i)
            cp16(stA + (uint32_t)(tid + i * 256) * 16, srcA + tid + i * 256);
        #pragma unroll
        for (int i = 0; i < 8; ++i)
            cp16(stB + (uint32_t)(tid + i * 256) * 16, srcB + tid + i * 256);
    };
    // fragment addresses within stage st, k-slice ksl
    auto aAddr = [&](int st, int ksl, int i) -> const uint4* {
        return sm + st * CHUNK_U4 + (size_t)(ksl * 8 + wm * 4 + i) * 32 + lane;
    };
    auto bAddr = [&](int st, int ksl, int j) -> const uint4* {
        return sm + st * CHUNK_U4 + 1024 + (size_t)(ksl * 16 + wn * 4 + j) * 32 + lane;
    };

    float acc[4][8][4];
    #pragma unroll
    for (int i = 0; i < 4; ++i)
        #pragma unroll
        for (int j = 0; j < 8; ++j)
            #pragma unroll
            for (int c = 0; c < 4; ++c) acc[i][j][c] = 0.f;

    // prologue: chunks 0,1 -> stages 0,1 (pair 0)
    fill(0, 0);
    fill(1, 1);
    asm volatile("cp.async.commit_group;" ::: "memory");
    asm volatile("cp.async.wait_group 0;" ::: "memory");
    __syncthreads();

    uint4 af[2][4], bf[2][4];
    #pragma unroll
    for (int i = 0; i < 4; ++i) af[0][i] = *aAddr(0, 0, i);
    #pragma unroll
    for (int j = 0; j < 4; ++j) bf[0][j] = *bAddr(0, 0, j);

    for (int s = 0; s < 64; ++s) {
        const int p = s & 1;                 // this super-step's stage pair {2p, 2p+1}
        // fill next super-step's chunks into the other pair (freed by last barrier)
        if (s < 63) {
            fill(2 * s + 2, 2 * (p ^ 1));
            fill(2 * s + 3, 2 * (p ^ 1) + 1);
        }
        asm volatile("cp.async.commit_group;" ::: "memory");

        // 8 k-slices: u>>2 selects chunk within pair, u&3 the k-slice
        #pragma unroll
        for (int u = 0; u < 8; ++u) {
            const int cur = u & 1;
            const int nxt = cur ^ 1;
            const int pu  = (u < 7) ? (u + 1) : 7;     // u=7: dead prefetch (safe)
            const int pst = 2 * p + (pu >> 2);
            const int pk  = pu & 3;
            #pragma unroll
            for (int i = 0; i < 4; ++i) af[nxt][i] = *aAddr(pst, pk, i);
            #pragma unroll
            for (int j = 0; j < 4; ++j) bf[nxt][j] = *bAddr(pst, pk, j);
            #pragma unroll
            for (int i = 0; i < 4; ++i) {
                const uint32_t* a = reinterpret_cast<const uint32_t*>(&af[cur][i]);
                #pragma unroll
                for (int j = 0; j < 4; ++j) {
                    mma_bf16(acc[i][2 * j + 0], a, bf[cur][j].x, bf[cur][j].z);
                    mma_bf16(acc[i][2 * j + 1], a, bf[cur][j].y, bf[cur][j].w);
                }
            }
        }

        asm volatile("cp.async.wait_group 0;" ::: "memory"); // next pair landed (had full window)
        __syncthreads();                                     // this pair free for overwrite
        if (s < 63) {                                        // load slot 0 of next super-step
            const int nst = 2 * (p ^ 1);
            #pragma unroll
            for (int i = 0; i < 4; ++i) af[0][i] = *aAddr(nst, 0, i);
            #pragma unroll
            for (int j = 0; j < 4; ++j) bf[0][j] = *bAddr(nst, 0, j);
        }
    }

    const int gid = lane >> 2, tig = lane & 3;
    float* wsbase = g_WS + ((size_t)kz << 20);
    #pragma unroll
    for (int i = 0; i < 4; ++i) {
        int row0 = mt * 128 + (wm * 4 + i) * 16 + gid;
        #pragma unroll
        for (int j = 0; j < 8; ++j) {
            int col = nt * 256 + (wn * 4 + (j >> 1)) * 16 + (j & 1) * 8 + tig * 2;
            float* d0 = wsbase + (size_t)row0 * 1024 + col;
            d0[0] = acc[i][j][0];
            d0[1] = acc[i][j][1];
            float* d1 = d0 + 8 * 1024;
            d1[0] = acc[i][j][2];
            d1[1] = acc[i][j][3];
        }
    }
}

// ---------------------------------------------------------------------------
// Kernel 3: reduce split-K partials + scale 1/(B*T). Deterministic.
// ---------------------------------------------------------------------------
__global__ void __launch_bounds__(256) stdp_reduce_kernel(float* __restrict__ out)
{
    int i = blockIdx.x * 256 + threadIdx.x;
    const float4* w = reinterpret_cast<const float4*>(g_WS);
    float4 a = w[i];
    float4 b = w[i + 262144];
    float4 c = w[i + 524288];
    float4 d = w[i + 786432];
    const float s = 1.0f / 16384.0f;
    float4 r;
    r.x = (a.x + b.x + c.x + d.x) * s;
    r.y = (a.y + b.y + c.y + d.y) * s;
    r.z = (a.z + b.z + c.z + d.z) * s;
    r.w = (a.w + b.w + c.w + d.w) * s;
    reinterpret_cast<float4*>(out)[i] = r;
}

// ---------------------------------------------------------------------------
extern "C" void kernel_launch(void* const* d_in, const int* in_sizes, int n_in,
                              void* d_out, int out_size)
{
    (void)in_sizes; (void)n_in; (void)out_size;
    const float* pre  = (const float*)d_in[0];
    const float* post = (const float*)d_in[1];
    float* out = (float*)d_out;

    stdp_scan_kernel<<<dim3(8, 32, 2), 128>>>(pre, post);

    cudaFuncSetAttribute(stdp_gemm_kernel,
                         cudaFuncAttributeMaxDynamicSharedMemorySize, GEMM_SMEM_B);
    stdp_gemm_kernel<<<dim3(8, 4, 4), 256, GEMM_SMEM_B>>>();

    stdp_reduce_kernel<<<1024, 256>>>(out);
}

// round 11
// speedup vs baseline: 1.1225x; 1.0002x over previous
#include <cuda_runtime.h>
#include <cuda_bf16.h>
#include <cstdint>
#include <cstddef>

// ============================================================================
// TripletSTDP: B=32, T=512, N_PRE=N_POST=1024.
// wu = (1/(B*T)) * (A @ B^T), K = 2*B*T = 32768
//   A[m][k]: k<16384 -> R trace of pre (decayed), k>=16384 -> pre spike
//   B[n][k]: k<16384 -> post spike,               k>=16384 -> -O trace of post
// A/B PRE-PERMUTED in mma.m16n8k16 fragment order (bf16).
// Scan = R9 (41us, closed). Reduce unchanged.
// GEMM: tile 128x128, 4 warps (2Mx2N, warp tile 64x64), 3-stage 32KB chunks
// -> 96KB smem -> 2 CTAs/SM to fill HMMA-pipe bubbles. grid (8,8,4).
// ============================================================================

static __device__ __align__(128) __nv_bfloat16 g_A[1024ull * 32768ull]; // 64 MB
static __device__ __align__(128) __nv_bfloat16 g_B[1024ull * 32768ull]; // 64 MB
static __device__ __align__(128) float         g_WS[4ull * 1024ull * 1024ull]; // split-K partials

// ---------------------------------------------------------------------------
__device__ __forceinline__ void mma_bf16(float* d, const uint32_t* a,
                                         uint32_t b0, uint32_t b1) {
    asm volatile(
        "mma.sync.aligned.m16n8k16.row.col.f32.bf16.bf16.f32 "
        "{%0,%1,%2,%3}, {%4,%5,%6,%7}, {%8,%9}, {%0,%1,%2,%3};"
        : "+f"(d[0]), "+f"(d[1]), "+f"(d[2]), "+f"(d[3])
        : "r"(a[0]), "r"(a[1]), "r"(a[2]), "r"(a[3]), "r"(b0), "r"(b1));
}
__device__ __forceinline__ uint32_t smem_u32(const void* p) {
    uint32_t a;
    asm("{ .reg .u64 t; cvta.to.shared.u64 t, %1; cvt.u32.u64 %0, t; }" : "=r"(a) : "l"(p));
    return a;
}
__device__ __forceinline__ void cp16(uint32_t dst, const void* src) {
    asm volatile("cp.async.cg.shared.global [%0], [%1], 16;" :: "r"(dst), "l"(src));
}

// ---------------------------------------------------------------------------
// Kernel 1: trace scan + fragment-layout store (R9 verbatim; 41us).
// ---------------------------------------------------------------------------
__global__ void __launch_bounds__(128) stdp_scan_kernel(const float* __restrict__ pre,
                                                        const float* __restrict__ post)
{
    const int side = blockIdx.z;
    const float* __restrict__ in = side ? post : pre;
    __nv_bfloat16* mat = side ? g_B : g_A;
    const int b   = blockIdx.y;
    const int bx  = blockIdx.x;
    const int tid = threadIdx.x;
    const int p0  = bx * 128;

    const float dA = 0.95122942f;                      // exp(-1/20)
    const float dB = side ? 0.99126643f : 0.99014786f; // exp(-1/114) / exp(-1/101)
    const float c1 = side ? 0.00525f : 0.005f;         // A_MINUS / A_PLUS
    const float c2 = 0.0001f;

    __shared__ __align__(16) float         sx[4][16 * 128];
    __shared__ __align__(16) __nv_bfloat16 s1[128][24];
    __shared__ __align__(16) __nv_bfloat16 s2[128][24];

    const float* base = in + (size_t)b * (512 * 1024) + p0;
    const uint32_t sxb = smem_u32(sx);

    auto fill = [&](int ch, int s) {
        const float* g = base + (size_t)ch * 16 * 1024;
        uint32_t st = sxb + (uint32_t)s * (16 * 128 * 4);
        #pragma unroll
        for (int i = 0; i < 4; ++i) {
            int idx = tid + i * 128;
            int r = idx >> 5, j = idx & 31;
            cp16(st + (uint32_t)(r * 512 + j * 16), g + (size_t)r * 1024 + j * 4);
        }
    };

    #pragma unroll
    for (int f = 0; f < 3; ++f) {
        fill(f, f);
        asm volatile("cp.async.commit_group;" ::: "memory");
    }

    float t1 = 0.f, t2 = 0.f;

    for (int ch = 0; ch < 32; ++ch) {
        asm volatile("cp.async.wait_group 2;" ::: "memory");
        __syncthreads();
        if (ch + 3 < 32) fill(ch + 3, (ch + 3) & 3);
        asm volatile("cp.async.commit_group;" ::: "memory");

        const float* x_s = sx[ch & 3];
        #pragma unroll
        for (int tt = 0; tt < 16; ++tt) {
            float x = x_s[tt * 128 + tid];
            t1 *= dA; t2 *= dB;
            float tr = fmaf(c2 * t1, t2, c1 * t1);
            s1[tid][tt] = __float2bfloat16(side ? x : tr);
            s2[tid][tt] = __float2bfloat16(side ? -tr : x);
            t1 += x; t2 += x;
        }
        __syncthreads();

        const int ks = b * 32 + ch;
        uint4* mat4 = reinterpret_cast<uint4*>(mat);
        #pragma unroll
        for (int it = 0; it < 2; ++it) {
            int f    = it * 128 + tid;
            int lane = f & 31;
            int frag = f >> 5;
            int gid  = lane >> 2, tig = lane & 3;
            int pr   = frag * 16 + gid;
            int tb   = tig * 2;
            uint4 w1, w2;
            w1.x = *(const uint32_t*)&s1[pr    ][tb    ];
            w1.y = *(const uint32_t*)&s1[pr + 8][tb    ];
            w1.z = *(const uint32_t*)&s1[pr    ][tb + 8];
            w1.w = *(const uint32_t*)&s1[pr + 8][tb + 8];
            w2.x = *(const uint32_t*)&s2[pr    ][tb    ];
            w2.y = *(const uint32_t*)&s2[pr + 8][tb    ];
            w2.z = *(const uint32_t*)&s2[pr    ][tb + 8];
            w2.w = *(const uint32_t*)&s2[pr + 8][tb + 8];
            size_t d16, half;
            if (side == 0) {
                d16  = ((size_t)(bx * 2048 + ks) * 8 + frag) * 32 + lane;
                half = 1024ull * 8 * 32;
            } else {
                d16  = ((size_t)((bx >> 1) * 2048 + ks) * 16 + (bx & 1) * 8 + frag) * 32 + lane;
                half = 1024ull * 16 * 32;
            }
            mat4[d16]        = w1;
            mat4[d16 + half] = w2;
        }
    }
}

// ---------------------------------------------------------------------------
// Kernel 2: bf16 mma.sync GEMM, 2 CTAs/SM. CTA tile 128x128, 4 warps (2Mx2N),
// warp tile 64x64, split-K=4 -> grid(8,8,4) = 256 CTAs (one wave at occ 2).
// 3-stage cp.async pipeline of 32KB k64 chunks; register fragment prefetch.
// ---------------------------------------------------------------------------
constexpr int      CHUNK_U4    = 2048;                       // 1024 A + 1024 B uint4
constexpr uint32_t GEMM_SMEM_B = 3 * CHUNK_U4 * 16;          // 98304 B

__global__ void __launch_bounds__(128, 2) stdp_gemm_kernel()
{
    extern __shared__ __align__(16) uint4 sm[];              // [3][2048]
    const int tid  = threadIdx.x;
    const int lane = tid & 31;
    const int wid  = tid >> 5;
    const int wm   = wid & 1;      // M direction (0..1)
    const int wn   = wid >> 1;     // N direction (0..1)
    const int mt   = blockIdx.x;   // 0..7 (128-row tile)
    const int nt   = blockIdx.y;   // 0..7 (128-col tile)
    const int kz   = blockIdx.z;   // 0..3 split-K

    // A: contiguous chunks. B: 8 of 16 n16-packs per k-step (half of a 256 tile).
    const uint4* gA = reinterpret_cast<const uint4*>(g_A)
                    + (size_t)(mt * 2048 + kz * 512) * 8 * 32;
    const uint4* gB = reinterpret_cast<const uint4*>(g_B)
                    + (size_t)((nt >> 1) * 2048 + kz * 512) * 16 * 32
                    + (size_t)(nt & 1) * 8 * 32;

    const uint32_t smb = smem_u32(sm);

    // fill chunk c into stage st: A (1024 u4 contiguous) + B (4 ksteps x 8 packs)
    auto fill = [&](int c, int st) {
        uint32_t stA = smb + (uint32_t)st * (CHUNK_U4 * 16);
        uint32_t stB = stA + 1024 * 16;
        const uint4* srcA = gA + (size_t)c * 1024;
        const uint4* srcB = gB + (size_t)c * 2048;     // 4 ksteps * 512 u4/kstep
        #pragma unroll
        for (int i = 0; i < 8; ++i) {
            int u = tid + i * 128;                     // 0..1023
            cp16(stA + (uint32_t)u * 16, srcA + u);
            cp16(stB + (uint32_t)u * 16, srcB + (size_t)(u >> 8) * 512 + (u & 255));
        }
    };
    auto aAddr = [&](int st, int ksl, int i) -> const uint4* {
        return sm + st * CHUNK_U4 + (size_t)(ksl * 8 + wm * 4 + i) * 32 + lane;
    };
    auto bAddr = [&](int st, int ksl, int j) -> const uint4* {
        return sm + st * CHUNK_U4 + 1024 + (size_t)(ksl * 8 + wn * 4 + j) * 32 + lane;
    };

    float acc[4][8][4];
    #pragma unroll
    for (int i = 0; i < 4; ++i)
        #pragma unroll
        for (int j = 0; j < 8; ++j)
            #pragma unroll
            for (int c = 0; c < 4; ++c) acc[i][j][c] = 0.f;

    // prologue: chunks 0,1 resident
    fill(0, 0);
    asm volatile("cp.async.commit_group;" ::: "memory");
    fill(1, 1);
    asm volatile("cp.async.commit_group;" ::: "memory");
    asm volatile("cp.async.wait_group 0;" ::: "memory");
    __syncthreads();

    uint4 af[2][4], bf[2][4];
    #pragma unroll
    for (int i = 0; i < 4; ++i) af[0][i] = *aAddr(0, 0, i);
    #pragma unroll
    for (int j = 0; j < 4; ++j) bf[0][j] = *bAddr(0, 0, j);

    int st_c = 0;                                      // stage of chunk c (c % 3)
    for (int c = 0; c < 128; ++c) {
        const int st_n = (st_c + 1 == 3) ? 0 : st_c + 1;   // stage of chunk c+1
        const int st_f = (st_n + 1 == 3) ? 0 : st_n + 1;   // stage of chunk c+2
        // fill chunk c+2 into st_f (freed by the barrier at end of iter c-1)
        if (c + 2 < 128) fill(c + 2, st_f);
        asm volatile("cp.async.commit_group;" ::: "memory");
        asm volatile("cp.async.wait_group 1;" ::: "memory"); // chunk c+1 resident

        #pragma unroll
        for (int ksl = 0; ksl < 4; ++ksl) {
            const int cur = ksl & 1;
            const int nxt = cur ^ 1;
            const int pst = (ksl == 3) ? st_n : st_c;  // prefetch c+1 slice 0 at ksl==3
            const int pk  = (ksl + 1) & 3;             // (c=127 prefetch dead but safe)
            #pragma unroll
            for (int i = 0; i < 4; ++i) af[nxt][i] = *aAddr(pst, pk, i);
            #pragma unroll
            for (int j = 0; j < 4; ++j) bf[nxt][j] = *bAddr(pst, pk, j);
            #pragma unroll
            for (int i = 0; i < 4; ++i) {
                const uint32_t* a = reinterpret_cast<const uint32_t*>(&af[cur][i]);
                #pragma unroll
                for (int j = 0; j < 4; ++j) {
                    mma_bf16(acc[i][2 * j + 0], a, bf[cur][j].x, bf[cur][j].z); // even n8
                    mma_bf16(acc[i][2 * j + 1], a, bf[cur][j].y, bf[cur][j].w); // odd n8
                }
            }
        }
        __syncthreads();   // all warps done reading chunk c -> stage st_c reusable
        st_c = st_n;
    }

    const int gid = lane >> 2, tig = lane & 3;
    float* wsbase = g_WS + ((size_t)kz << 20);
    #pragma unroll
    for (int i = 0; i < 4; ++i) {
        int row0 = mt * 128 + (wm * 4 + i) * 16 + gid;
        #pragma unroll
        for (int j = 0; j < 8; ++j) {
            int col = nt * 128 + (wn * 4 + (j >> 1)) * 16 + (j & 1) * 8 + tig * 2;
            float* d0 = wsbase + (size_t)row0 * 1024 + col;
            d0[0] = acc[i][j][0];
            d0[1] = acc[i][j][1];
            float* d1 = d0 + 8 * 1024;
            d1[0] = acc[i][j][2];
            d1[1] = acc[i][j][3];
        }
    }
}

// ---------------------------------------------------------------------------
// Kernel 3: reduce split-K partials + scale 1/(B*T). Deterministic.
// ---------------------------------------------------------------------------
__global__ void __launch_bounds__(256) stdp_reduce_kernel(float* __restrict__ out)
{
    int i = blockIdx.x * 256 + threadIdx.x;
    const float4* w = reinterpret_cast<const float4*>(g_WS);
    float4 a = w[i];
    float4 b = w[i + 262144];
    float4 c = w[i + 524288];
    float4 d = w[i + 786432];
    const float s = 1.0f / 16384.0f;
    float4 r;
    r.x = (a.x + b.x + c.x + d.x) * s;
    r.y = (a.y + b.y + c.y + d.y) * s;
    r.z = (a.z + b.z + c.z + d.z) * s;
    r.w = (a.w + b.w + c.w + d.w) * s;
    reinterpret_cast<float4*>(out)[i] = r;
}

// ---------------------------------------------------------------------------
extern "C" void kernel_launch(void* const* d_in, const int* in_sizes, int n_in,
                              void* d_out, int out_size)
{
    (void)in_sizes; (void)n_in; (void)out_size;
    const float* pre  = (const float*)d_in[0];
    const float* post = (const float*)d_in[1];
    float* out = (float*)d_out;

    stdp_scan_kernel<<<dim3(8, 32, 2), 128>>>(pre, post);

    cudaFuncSetAttribute(stdp_gemm_kernel,
                         cudaFuncAttributeMaxDynamicSharedMemorySize, GEMM_SMEM_B);
    stdp_gemm_kernel<<<dim3(8, 8, 4), 128, GEMM_SMEM_B>>>();

    stdp_reduce_kernel<<<1024, 256>>>(out);
}

// round 12
// speedup vs baseline: 1.1479x; 1.0226x over previous
#include <cuda_runtime.h>
#include <cuda_bf16.h>
#include <cstdint>
#include <cstddef>

// ============================================================================
// TripletSTDP: B=32, T=512, N_PRE=N_POST=1024.
// wu = (1/(B*T)) * (A @ B^T), K = 2*B*T = 32768
//   A[m][k]: k<16384 -> R trace of pre (decayed), k>=16384 -> pre spike
//   B[n][k]: k<16384 -> post spike,               k>=16384 -> -O trace of post
// A/B PRE-PERMUTED in mma.m16n8k16 fragment order (bf16).
// Pipeline overlap: scan(batches 0-15) -> [gemm slices {0,1,4,5} on stream1
// || scan(batches 16-31)] -> gemm slices {2,3,6,7} -> reduce. Split-K=8.
// GEMM body = R10 super-chunked 128x256 kernel (best known).
// ============================================================================

static __device__ __align__(128) __nv_bfloat16 g_A[1024ull * 32768ull]; // 64 MB
static __device__ __align__(128) __nv_bfloat16 g_B[1024ull * 32768ull]; // 64 MB
static __device__ __align__(128) float         g_WS[8ull * 1024ull * 1024ull]; // 8 split-K partials

// ---------------------------------------------------------------------------
__device__ __forceinline__ void mma_bf16(float* d, const uint32_t* a,
                                         uint32_t b0, uint32_t b1) {
    asm volatile(
        "mma.sync.aligned.m16n8k16.row.col.f32.bf16.bf16.f32 "
        "{%0,%1,%2,%3}, {%4,%5,%6,%7}, {%8,%9}, {%0,%1,%2,%3};"
        : "+f"(d[0]), "+f"(d[1]), "+f"(d[2]), "+f"(d[3])
        : "r"(a[0]), "r"(a[1]), "r"(a[2]), "r"(a[3]), "r"(b0), "r"(b1));
}
__device__ __forceinline__ uint32_t smem_u32(const void* p) {
    uint32_t a;
    asm("{ .reg .u64 t; cvta.to.shared.u64 t, %1; cvt.u32.u64 %0, t; }" : "=r"(a) : "l"(p));
    return a;
}
__device__ __forceinline__ void cp16(uint32_t dst, const void* src) {
    asm volatile("cp.async.cg.shared.global [%0], [%1], 16;" :: "r"(dst), "l"(src));
}

// ---------------------------------------------------------------------------
// Kernel 1: trace scan + fragment-layout store (R9 body + batch offset).
// grid (8, 16, 2): 16 batches per launch.
// ---------------------------------------------------------------------------
__global__ void __launch_bounds__(128) stdp_scan_kernel(const float* __restrict__ pre,
                                                        const float* __restrict__ post,
                                                        int b0)
{
    const int side = blockIdx.z;
    const float* __restrict__ in = side ? post : pre;
    __nv_bfloat16* mat = side ? g_B : g_A;
    const int b   = blockIdx.y + b0;
    const int bx  = blockIdx.x;
    const int tid = threadIdx.x;
    const int p0  = bx * 128;

    const float dA = 0.95122942f;                      // exp(-1/20)
    const float dB = side ? 0.99126643f : 0.99014786f; // exp(-1/114) / exp(-1/101)
    const float c1 = side ? 0.00525f : 0.005f;         // A_MINUS / A_PLUS
    const float c2 = 0.0001f;

    __shared__ __align__(16) float         sx[4][16 * 128];
    __shared__ __align__(16) __nv_bfloat16 s1[128][24];
    __shared__ __align__(16) __nv_bfloat16 s2[128][24];

    const float* base = in + (size_t)b * (512 * 1024) + p0;
    const uint32_t sxb = smem_u32(sx);

    auto fill = [&](int ch, int s) {
        const float* g = base + (size_t)ch * 16 * 1024;
        uint32_t st = sxb + (uint32_t)s * (16 * 128 * 4);
        #pragma unroll
        for (int i = 0; i < 4; ++i) {
            int idx = tid + i * 128;
            int r = idx >> 5, j = idx & 31;
            cp16(st + (uint32_t)(r * 512 + j * 16), g + (size_t)r * 1024 + j * 4);
        }
    };

    #pragma unroll
    for (int f = 0; f < 3; ++f) {
        fill(f, f);
        asm volatile("cp.async.commit_group;" ::: "memory");
    }

    float t1 = 0.f, t2 = 0.f;

    for (int ch = 0; ch < 32; ++ch) {
        asm volatile("cp.async.wait_group 2;" ::: "memory");
        __syncthreads();
        if (ch + 3 < 32) fill(ch + 3, (ch + 3) & 3);
        asm volatile("cp.async.commit_group;" ::: "memory");

        const float* x_s = sx[ch & 3];
        #pragma unroll
        for (int tt = 0; tt < 16; ++tt) {
            float x = x_s[tt * 128 + tid];
            t1 *= dA; t2 *= dB;
            float tr = fmaf(c2 * t1, t2, c1 * t1);
            s1[tid][tt] = __float2bfloat16(side ? x : tr);
            s2[tid][tt] = __float2bfloat16(side ? -tr : x);
            t1 += x; t2 += x;
        }
        __syncthreads();

        const int ks = b * 32 + ch;
        uint4* mat4 = reinterpret_cast<uint4*>(mat);
        #pragma unroll
        for (int it = 0; it < 2; ++it) {
            int f    = it * 128 + tid;
            int lane = f & 31;
            int frag = f >> 5;
            int gid  = lane >> 2, tig = lane & 3;
            int pr   = frag * 16 + gid;
            int tb   = tig * 2;
            uint4 w1, w2;
            w1.x = *(const uint32_t*)&s1[pr    ][tb    ];
            w1.y = *(const uint32_t*)&s1[pr + 8][tb    ];
            w1.z = *(const uint32_t*)&s1[pr    ][tb + 8];
            w1.w = *(const uint32_t*)&s1[pr + 8][tb + 8];
            w2.x = *(const uint32_t*)&s2[pr    ][tb    ];
            w2.y = *(const uint32_t*)&s2[pr + 8][tb    ];
            w2.z = *(const uint32_t*)&s2[pr    ][tb + 8];
            w2.w = *(const uint32_t*)&s2[pr + 8][tb + 8];
            size_t d16, half;
            if (side == 0) {
                d16  = ((size_t)(bx * 2048 + ks) * 8 + frag) * 32 + lane;
                half = 1024ull * 8 * 32;
            } else {
                d16  = ((size_t)((bx >> 1) * 2048 + ks) * 16 + (bx & 1) * 8 + frag) * 32 + lane;
                half = 1024ull * 16 * 32;
            }
            mat4[d16]        = w1;
            mat4[d16 + half] = w2;
        }
    }
}

// ---------------------------------------------------------------------------
// Kernel 2: bf16 mma.sync GEMM, super-chunked (R10 body). CTA 128x256,
// 8 warps (2Mx4N), warp tile 64x64. Split-K=8 (4096 k per CTA = 64 chunks =
// 32 super-steps). Per launch: grid (8,4,4) = 128 CTAs.
//   pass 0 -> slices {0,1,4,5}; pass 1 -> slices {2,3,6,7}.
// ---------------------------------------------------------------------------
constexpr int      CHUNK_U4    = 3072;                       // 1024 A + 2048 B uint4
constexpr uint32_t GEMM_SMEM_B = 4 * CHUNK_U4 * 16;          // 196608 B

__global__ void __launch_bounds__(256, 1) stdp_gemm_kernel(int pass)
{
    extern __shared__ __align__(16) uint4 sm[];              // [4][3072]
    const int tid  = threadIdx.x;
    const int lane = tid & 31;
    const int wid  = tid >> 5;
    const int wm   = wid & 1;
    const int wn   = wid >> 1;
    const int mt   = blockIdx.x;
    const int nt   = blockIdx.y;
    const int z    = blockIdx.z;
    const int slice = (pass << 1) + (z & 1) + ((z >> 1) << 2); // {0,1,4,5}/{2,3,6,7}

    const uint4* gA = reinterpret_cast<const uint4*>(g_A)
                    + (size_t)(mt * 2048 + slice * 256) * 8 * 32;
    const uint4* gB = reinterpret_cast<const uint4*>(g_B)
                    + (size_t)(nt * 2048 + slice * 256) * 16 * 32;

    const uint32_t smb = smem_u32(sm);

    auto fill = [&](int c, int st) {
        uint32_t stA = smb + (uint32_t)st * (CHUNK_U4 * 16);
        uint32_t stB = stA + 1024 * 16;
        const uint4* srcA = gA + (size_t)c * 1024;
        const uint4* srcB = gB + (size_t)c * 2048;
        #pragma unroll
        for (int i = 0; i < 4; ++i)
            cp16(stA + (uint32_t)(tid + i * 256) * 16, srcA + tid + i * 256);
        #pragma unroll
        for (int i = 0; i < 8; ++i)
            cp16(stB + (uint32_t)(tid + i * 256) * 16, srcB + tid + i * 256);
    };
    auto aAddr = [&](int st, int ksl, int i) -> const uint4* {
        return sm + st * CHUNK_U4 + (size_t)(ksl * 8 + wm * 4 + i) * 32 + lane;
    };
    auto bAddr = [&](int st, int ksl, int j) -> const uint4* {
        return sm + st * CHUNK_U4 + 1024 + (size_t)(ksl * 16 + wn * 4 + j) * 32 + lane;
    };

    float acc[4][8][4];
    #pragma unroll
    for (int i = 0; i < 4; ++i)
        #pragma unroll
        for (int j = 0; j < 8; ++j)
            #pragma unroll
            for (int c = 0; c < 4; ++c) acc[i][j][c] = 0.f;

    fill(0, 0);
    fill(1, 1);
    asm volatile("cp.async.commit_group;" ::: "memory");
    asm volatile("cp.async.wait_group 0;" ::: "memory");
    __syncthreads();

    uint4 af[2][4], bf[2][4];
    #pragma unroll
    for (int i = 0; i < 4; ++i) af[0][i] = *aAddr(0, 0, i);
    #pragma unroll
    for (int j = 0; j < 4; ++j) bf[0][j] = *bAddr(0, 0, j);

    for (int s = 0; s < 32; ++s) {
        const int p = s & 1;
        if (s < 31) {
            fill(2 * s + 2, 2 * (p ^ 1));
            fill(2 * s + 3, 2 * (p ^ 1) + 1);
        }
        asm volatile("cp.async.commit_group;" ::: "memory");

        #pragma unroll
        for (int u = 0; u < 8; ++u) {
            const int cur = u & 1;
            const int nxt = cur ^ 1;
            const int pu  = (u < 7) ? (u + 1) : 7;     // u=7: dead prefetch (safe)
            const int pst = 2 * p + (pu >> 2);
            const int pk  = pu & 3;
            #pragma unroll
            for (int i = 0; i < 4; ++i) af[nxt][i] = *aAddr(pst, pk, i);
            #pragma unroll
            for (int j = 0; j < 4; ++j) bf[nxt][j] = *bAddr(pst, pk, j);
            #pragma unroll
            for (int i = 0; i < 4; ++i) {
                const uint32_t* a = reinterpret_cast<const uint32_t*>(&af[cur][i]);
                #pragma unroll
                for (int j = 0; j < 4; ++j) {
                    mma_bf16(acc[i][2 * j + 0], a, bf[cur][j].x, bf[cur][j].z);
                    mma_bf16(acc[i][2 * j + 1], a, bf[cur][j].y, bf[cur][j].w);
                }
            }
        }

        asm volatile("cp.async.wait_group 0;" ::: "memory");
        __syncthreads();
        if (s < 31) {
            const int nst = 2 * (p ^ 1);
            #pragma unroll
            for (int i = 0; i < 4; ++i) af[0][i] = *aAddr(nst, 0, i);
            #pragma unroll
            for (int j = 0; j < 4; ++j) bf[0][j] = *bAddr(nst, 0, j);
        }
    }

    const int gid = lane >> 2, tig = lane & 3;
    float* wsbase = g_WS + ((size_t)slice << 20);
    #pragma unroll
    for (int i = 0; i < 4; ++i) {
        int row0 = mt * 128 + (wm * 4 + i) * 16 + gid;
        #pragma unroll
        for (int j = 0; j < 8; ++j) {
            int col = nt * 256 + (wn * 4 + (j >> 1)) * 16 + (j & 1) * 8 + tig * 2;
            float* d0 = wsbase + (size_t)row0 * 1024 + col;
            d0[0] = acc[i][j][0];
            d0[1] = acc[i][j][1];
            float* d1 = d0 + 8 * 1024;
            d1[0] = acc[i][j][2];
            d1[1] = acc[i][j][3];
        }
    }
}

// ---------------------------------------------------------------------------
// Kernel 3: reduce 8 split-K partials + scale 1/(B*T). Deterministic.
// ---------------------------------------------------------------------------
__global__ void __launch_bounds__(256) stdp_reduce_kernel(float* __restrict__ out)
{
    int i = blockIdx.x * 256 + threadIdx.x;
    const float4* w = reinterpret_cast<const float4*>(g_WS);
    float x = 0.f, y = 0.f, z = 0.f, u = 0.f;
    #pragma unroll
    for (int j = 0; j < 8; ++j) {
        float4 v = w[i + j * 262144];
        x += v.x; y += v.y; z += v.z; u += v.w;
    }
    const float s = 1.0f / 16384.0f;
    float4 r; r.x = x * s; r.y = y * s; r.z = z * s; r.w = u * s;
    reinterpret_cast<float4*>(out)[i] = r;
}

// ---------------------------------------------------------------------------
extern "C" void kernel_launch(void* const* d_in, const int* in_sizes, int n_in,
                              void* d_out, int out_size)
{
    (void)in_sizes; (void)n_in; (void)out_size;
    const float* pre  = (const float*)d_in[0];
    const float* post = (const float*)d_in[1];
    float* out = (float*)d_out;

    static cudaStream_t s1 = nullptr;
    static cudaEvent_t ev0 = nullptr, ev1 = nullptr, ev2 = nullptr;
    if (s1 == nullptr) {
        cudaStreamCreateWithFlags(&s1, cudaStreamNonBlocking);
        cudaEventCreateWithFlags(&ev0, cudaEventDisableTiming);
        cudaEventCreateWithFlags(&ev1, cudaEventDisableTiming);
        cudaEventCreateWithFlags(&ev2, cudaEventDisableTiming);
        cudaFuncSetAttribute(stdp_gemm_kernel,
                             cudaFuncAttributeMaxDynamicSharedMemorySize, GEMM_SMEM_B);
    }

    // scan batches 0-15 (enables K slices {0,1,4,5})
    stdp_scan_kernel<<<dim3(8, 16, 2), 128>>>(pre, post, 0);
    cudaEventRecord(ev0, 0);
    cudaStreamWaitEvent(s1, ev0, 0);

    // GEMM pass 0 on stream s1, overlapping scan of batches 16-31 below
    stdp_gemm_kernel<<<dim3(8, 4, 4), 256, GEMM_SMEM_B, s1>>>(0);

    stdp_scan_kernel<<<dim3(8, 16, 2), 128>>>(pre, post, 16);
    cudaEventRecord(ev1, 0);
    cudaStreamWaitEvent(s1, ev1, 0);

    // GEMM pass 1 (slices {2,3,6,7})
    stdp_gemm_kernel<<<dim3(8, 4, 4), 256, GEMM_SMEM_B, s1>>>(1);
    cudaEventRecord(ev2, s1);
    cudaStreamWaitEvent(0, ev2, 0);

    stdp_reduce_kernel<<<1024, 256>>>(out);
}